// round 6
// baseline (speedup 1.0000x reference)
#include <cuda_runtime.h>
#include <cstdint>
#include <math.h>

// Problem dims (fixed by the reference)
static constexpr int B_ = 16;
static constexpr int C_ = 256;
static constexpr int N_ = 4096;
static constexpr int M_ = 1024;
static constexpr float EPS_ = 1e-5f;

// ---------------- scratch (static device globals; no allocation) ----------
__device__ float g_mean[B_ * C_];
__device__ float g_score[B_ * N_];
__device__ int   g_idx[B_ * 2 * M_];
__device__ float g_Xs[(size_t)B_ * C_ * M_];
__device__ float g_Xg[(size_t)B_ * C_ * M_];
__device__ float g_Q[(size_t)B_ * C_ * N_];
__device__ float g_K[(size_t)B_ * C_ * M_];
__device__ float g_V[(size_t)B_ * C_ * M_];
__device__ float g_WV[(size_t)B_ * C_ * M_];  // Wo @ V
__device__ float g_ys[(size_t)B_ * C_ * N_];
__device__ float g_yg[(size_t)B_ * C_ * N_];
__device__ float g_Z[(size_t)B_ * C_ * N_];
__device__ float g_mu[C_];
__device__ float g_rstd[C_];

// ---------------- helpers --------------------------------------------------
__device__ __forceinline__ uint32_t f2tf32(float f) {
    uint32_t u;
    asm("cvt.rna.tf32.f32 %0, %1;" : "=r"(u) : "f"(f));
    return u;
}
__device__ __forceinline__ void mma_tf32(float* c, const uint32_t* a, const uint32_t* b) {
    asm volatile(
        "mma.sync.aligned.m16n8k8.row.col.f32.tf32.tf32.f32 "
        "{%0,%1,%2,%3}, {%4,%5,%6,%7}, {%8,%9}, {%0,%1,%2,%3};"
        : "+f"(c[0]), "+f"(c[1]), "+f"(c[2]), "+f"(c[3])
        : "r"(a[0]), "r"(a[1]), "r"(a[2]), "r"(a[3]), "r"(b[0]), "r"(b[1]));
}
__device__ __forceinline__ uint32_t smem_u32(const void* p) {
    uint32_t a;
    asm("{ .reg .u64 t; cvta.to.shared.u64 t, %1; cvt.u32.u64 %0, t; }"
        : "=r"(a) : "l"(p));
    return a;
}
__device__ __forceinline__ void cp16(uint32_t saddr, const float* g) {
    asm volatile("cp.async.cg.shared.global [%0], [%1], 16;" :: "r"(saddr), "l"(g));
}

// ================== pipelined warp-MMA tf32 generic strided GEMM ==========
// D[i,j] = scale*(acc + bias[i]) [+ D_old]
// A(i,k) = A[i*As0 + k*As1]; B(j,k) = B[j*Bs0 + k*Bs1]; one stride is 1.
// Block tile 128x128, 4 warps (64x64 each), BK=32. Md,Nd %128; Kd %32.
#define BM 128
#define BN 128
#define BK 32
#define SKC 36   // smem row stride (words), k-contig layout [i][k]
#define SIC 136  // smem row stride (words), i-contig layout [k][i]
#define OPW 4608 // words per operand per stage = max(128*36, 32*136)

__device__ __forceinline__ void stage_tile(const float* __restrict__ src,
                                           long s0, long s1, int kc,
                                           uint32_t sbase, int t0, int kt, int tid) {
    if (kc) {  // k contiguous -> smem [i][k], stride SKC
#pragma unroll
        for (int it = 0; it < 8; it++) {
            int q = tid + it * 128;
            int row = q >> 3, kq = (q & 7) << 2;
            cp16(sbase + (uint32_t)(row * SKC + kq) * 4u,
                 src + (long)(t0 + row) * s0 + kt + kq);
        }
    } else {   // i contiguous -> smem [k][i], stride SIC
#pragma unroll
        for (int it = 0; it < 8; it++) {
            int q = tid + it * 128;
            int kr = q >> 5, iq = (q & 31) << 2;
            cp16(sbase + (uint32_t)(kr * SIC + iq) * 4u,
                 src + (long)(t0 + iq) + (long)(kt + kr) * s1);
        }
    }
}

__global__ void __launch_bounds__(128, 2)
tc_gemm_kernel(const float* __restrict__ A, long Ab, long As0, long As1,
               const float* __restrict__ Bp, long Bb, long Bs0, long Bs1,
               float* __restrict__ Cp, long Cb, long Cs0,
               const float* __restrict__ bias,
               float scale, int accumulate, int Kd) {
    extern __shared__ uint32_t sm[];

    const int tid = threadIdx.x;
    const int wid = tid >> 5;
    const int lane = tid & 31;
    const int g = lane >> 2;
    const int t4 = lane & 3;
    const int wm = wid & 1;
    const int wn = wid >> 1;

    const int aKc = (As1 == 1);
    const int bKc = (Bs1 == 1);

    const int bz = blockIdx.z;
    A += (size_t)bz * Ab;
    Bp += (size_t)bz * Bb;
    Cp += (size_t)bz * Cb;

    const int i0 = blockIdx.y * BM;
    const int j0 = blockIdx.x * BN;

    const uint32_t smbase = smem_u32(sm);

    float acc[4][8][4];
#pragma unroll
    for (int a = 0; a < 4; a++)
#pragma unroll
        for (int b = 0; b < 8; b++)
#pragma unroll
            for (int c = 0; c < 4; c++) acc[a][b][c] = 0.f;

    const int nch = Kd >> 5;

    stage_tile(A, As0, As1, aKc, smbase, i0, 0, tid);
    stage_tile(Bp, Bs0, Bs1, bKc, smbase + OPW * 4u, j0, 0, tid);
    asm volatile("cp.async.commit_group;" ::: "memory");

    for (int ch = 0; ch < nch; ch++) {
        if (ch + 1 < nch) {
            uint32_t sb = smbase + (uint32_t)(((ch + 1) & 1) * 2 * OPW) * 4u;
            stage_tile(A, As0, As1, aKc, sb, i0, (ch + 1) * BK, tid);
            stage_tile(Bp, Bs0, Bs1, bKc, sb + OPW * 4u, j0, (ch + 1) * BK, tid);
        }
        asm volatile("cp.async.commit_group;" ::: "memory");
        asm volatile("cp.async.wait_group 1;" ::: "memory");
        __syncthreads();

        const uint32_t* sA = sm + (ch & 1) * 2 * OPW;
        const uint32_t* sB = sA + OPW;

#pragma unroll
        for (int ks = 0; ks < BK; ks += 8) {
            uint32_t af[4][4];
            if (aKc) {
#pragma unroll
                for (int mt = 0; mt < 4; mt++) {
                    int rb = wm * 64 + mt * 16 + g;
                    af[mt][0] = f2tf32(__uint_as_float(sA[(rb    ) * SKC + ks + t4    ]));
                    af[mt][1] = f2tf32(__uint_as_float(sA[(rb + 8) * SKC + ks + t4    ]));
                    af[mt][2] = f2tf32(__uint_as_float(sA[(rb    ) * SKC + ks + t4 + 4]));
                    af[mt][3] = f2tf32(__uint_as_float(sA[(rb + 8) * SKC + ks + t4 + 4]));
                }
            } else {
#pragma unroll
                for (int mt = 0; mt < 4; mt++) {
                    int rb = wm * 64 + mt * 16 + g;
                    af[mt][0] = f2tf32(__uint_as_float(sA[(ks + t4    ) * SIC + rb    ]));
                    af[mt][1] = f2tf32(__uint_as_float(sA[(ks + t4    ) * SIC + rb + 8]));
                    af[mt][2] = f2tf32(__uint_as_float(sA[(ks + t4 + 4) * SIC + rb    ]));
                    af[mt][3] = f2tf32(__uint_as_float(sA[(ks + t4 + 4) * SIC + rb + 8]));
                }
            }
            uint32_t bf[8][2];
            if (bKc) {
#pragma unroll
                for (int nt = 0; nt < 8; nt++) {
                    int cb = wn * 64 + nt * 8 + g;
                    bf[nt][0] = f2tf32(__uint_as_float(sB[(cb) * SKC + ks + t4    ]));
                    bf[nt][1] = f2tf32(__uint_as_float(sB[(cb) * SKC + ks + t4 + 4]));
                }
            } else {
#pragma unroll
                for (int nt = 0; nt < 8; nt++) {
                    int cb = wn * 64 + nt * 8 + g;
                    bf[nt][0] = f2tf32(__uint_as_float(sB[(ks + t4    ) * SIC + cb]));
                    bf[nt][1] = f2tf32(__uint_as_float(sB[(ks + t4 + 4) * SIC + cb]));
                }
            }
#pragma unroll
            for (int mt = 0; mt < 4; mt++)
#pragma unroll
                for (int nt = 0; nt < 8; nt++)
                    mma_tf32(acc[mt][nt], af[mt], bf[nt]);
        }
        __syncthreads();
    }

#pragma unroll
    for (int mt = 0; mt < 4; mt++) {
#pragma unroll
        for (int half = 0; half < 2; half++) {
            int i = i0 + wm * 64 + mt * 16 + g + half * 8;
            float bi = bias ? scale * bias[i] : 0.f;
#pragma unroll
            for (int nt = 0; nt < 8; nt++) {
                int j = j0 + wn * 64 + nt * 8 + t4 * 2;
                long off = (long)i * Cs0 + j;
                float2 v;
                v.x = scale * acc[mt][nt][half * 2 + 0] + bi;
                v.y = scale * acc[mt][nt][half * 2 + 1] + bi;
                if (accumulate) {
                    float2 o2 = *(const float2*)(Cp + off);
                    v.x += o2.x; v.y += o2.y;
                }
                *(float2*)(Cp + off) = v;
            }
        }
    }
}

// ============ fused attention: S = exp(Q^T K), rowsum, Y = WV E^T ==========
// Per CTA: 128 n-rows (n0), 128 c-cols (c0), batch b. Loops over 8 m-tiles.
// Q: [C][N] (prescaled 1/sqrt(C), +bq); K: [C][M]; WV: [C][M] (= Wo@(Wv Xctx+bv)).
// Output: yout[c, n] = (sum_m WV[c,m] exp(S[n,m])) / (sum_m exp(S[n,m])) + bo[c] + x[c,n]
//
// SMEM words: QK staging 2 stages x 2 ops x (32*136)=17408 | E 128*132=16896
//             WV 128*132=16896 | rowsum 256.  Total 51456 words = 205824 B.
#define ATTN_SMEM 205824

__device__ __forceinline__ void stage_ic256(const float* __restrict__ src,
                                            long s1, int t0, int kt,
                                            uint32_t sbase, int tid) {
    // i-contig [k 32][i 128] stride 136, 256 threads
#pragma unroll
    for (int it = 0; it < 4; it++) {
        int q = tid + it * 256;
        int kr = q >> 5, iq = (q & 31) << 2;
        cp16(sbase + (uint32_t)(kr * SIC + iq) * 4u,
             src + (long)(kt + kr) * s1 + t0 + iq);
    }
}

__global__ void __launch_bounds__(256, 1)
attn_kernel(const float* __restrict__ Qg, const float* __restrict__ Kg,
            const float* __restrict__ WVg, const float* __restrict__ x,
            const float* __restrict__ bo, float* __restrict__ yout) {
    extern __shared__ uint32_t sm[];
    const int tid = threadIdx.x;
    const int wid = tid >> 5;
    const int lane = tid & 31;
    const int g = lane >> 2;
    const int t4 = lane & 3;
    const int wm = wid & 1;    // 2 warp-rows x 4 warp-cols; warp tile 64x32
    const int wn = wid >> 1;
    const int b = blockIdx.z;
    const int n0 = blockIdx.x * 128;
    const int c0 = blockIdx.y * 128;

    Qg   += (size_t)b * C_ * N_;
    Kg   += (size_t)b * C_ * M_;
    WVg  += (size_t)b * C_ * M_;
    x    += (size_t)b * C_ * N_;
    yout += (size_t)b * C_ * N_;

    const uint32_t smb = smem_u32(sm);
    const uint32_t wvb = smb + 34304u * 4u;
    uint32_t* const sE = sm + 17408;
    const float* const fE = (const float*)sE;
    const float* const fWV = (const float*)(sm + 34304);
    float* const rs_sm = (float*)(sm + 51200);

    float yacc[4][4][4];
#pragma unroll
    for (int a = 0; a < 4; a++)
#pragma unroll
        for (int bq = 0; bq < 4; bq++)
#pragma unroll
            for (int c = 0; c < 4; c++) yacc[a][bq][c] = 0.f;

    float rs = 0.f;
    const int rsrow = tid >> 1;
    const int rshalf = tid & 1;

    for (int m0 = 0; m0 < M_; m0 += 128) {
        // prefetch WV tile [c 128][m 128], k-contig stride 132 (group issued first)
#pragma unroll
        for (int it = 0; it < 16; it++) {
            int q = tid + it * 256;
            int r = q >> 5, mq = (q & 31) << 2;
            cp16(wvb + (uint32_t)(r * 132 + mq) * 4u,
                 WVg + (size_t)(c0 + r) * M_ + m0 + mq);
        }
        asm volatile("cp.async.commit_group;" ::: "memory");

        // ---- S phase: sacc = Q^T K over d=256, 8 chunks of 32 ----
        float sacc[4][4][4];
#pragma unroll
        for (int a = 0; a < 4; a++)
#pragma unroll
            for (int bq = 0; bq < 4; bq++)
#pragma unroll
                for (int c = 0; c < 4; c++) sacc[a][bq][c] = 0.f;

        stage_ic256(Qg, N_, n0, 0, smb, tid);
        stage_ic256(Kg, M_, m0, 0, smb + 4352u * 4u, tid);
        asm volatile("cp.async.commit_group;" ::: "memory");

        for (int ch = 0; ch < 8; ch++) {
            if (ch < 7) {
                uint32_t sb = smb + (uint32_t)(((ch + 1) & 1) * 8704u) * 4u;
                stage_ic256(Qg, N_, n0, (ch + 1) * 32, sb, tid);
                stage_ic256(Kg, M_, m0, (ch + 1) * 32, sb + 4352u * 4u, tid);
            }
            asm volatile("cp.async.commit_group;" ::: "memory");
            asm volatile("cp.async.wait_group 1;" ::: "memory");
            __syncthreads();
            const uint32_t* sA = sm + (ch & 1) * 8704;
            const uint32_t* sB = sA + 4352;
#pragma unroll
            for (int ks = 0; ks < 32; ks += 8) {
                uint32_t af[4][4], bf[4][2];
#pragma unroll
                for (int mt = 0; mt < 4; mt++) {
                    int rb = wm * 64 + mt * 16 + g;
                    af[mt][0] = f2tf32(__uint_as_float(sA[(ks + t4    ) * SIC + rb    ]));
                    af[mt][1] = f2tf32(__uint_as_float(sA[(ks + t4    ) * SIC + rb + 8]));
                    af[mt][2] = f2tf32(__uint_as_float(sA[(ks + t4 + 4) * SIC + rb    ]));
                    af[mt][3] = f2tf32(__uint_as_float(sA[(ks + t4 + 4) * SIC + rb + 8]));
                }
#pragma unroll
                for (int nt = 0; nt < 4; nt++) {
                    int cb = wn * 32 + nt * 8 + g;
                    bf[nt][0] = f2tf32(__uint_as_float(sB[(ks + t4    ) * SIC + cb]));
                    bf[nt][1] = f2tf32(__uint_as_float(sB[(ks + t4 + 4) * SIC + cb]));
                }
#pragma unroll
                for (int mt = 0; mt < 4; mt++)
#pragma unroll
                    for (int nt = 0; nt < 4; nt++)
                        mma_tf32(sacc[mt][nt], af[mt], bf[nt]);
            }
            __syncthreads();
        }

        // ---- exp -> E smem (tf32 bits) ----
#pragma unroll
        for (int mt = 0; mt < 4; mt++)
#pragma unroll
            for (int half = 0; half < 2; half++) {
                int i = wm * 64 + mt * 16 + g + half * 8;
#pragma unroll
                for (int nt = 0; nt < 4; nt++) {
                    int j = wn * 32 + nt * 8 + t4 * 2;
                    sE[i * 132 + j]     = f2tf32(__expf(sacc[mt][nt][half * 2 + 0]));
                    sE[i * 132 + j + 1] = f2tf32(__expf(sacc[mt][nt][half * 2 + 1]));
                }
            }
        asm volatile("cp.async.wait_group 0;" ::: "memory");
        __syncthreads();

        // ---- partial row sums from E ----
        {
            const float* er = fE + rsrow * 132 + rshalf * 64;
            float s = 0.f;
#pragma unroll 16
            for (int q = 0; q < 64; q++) s += er[q];
            rs += s;
        }

        // ---- Y phase: yacc += E(n,m) * WV(c,m), contraction m=128 ----
#pragma unroll
        for (int km = 0; km < 128; km += 8) {
            uint32_t af[4][4], bf[4][2];
#pragma unroll
            for (int mt = 0; mt < 4; mt++) {
                int rb = wm * 64 + mt * 16 + g;
                af[mt][0] = sE[(rb    ) * 132 + km + t4    ];
                af[mt][1] = sE[(rb + 8) * 132 + km + t4    ];
                af[mt][2] = sE[(rb    ) * 132 + km + t4 + 4];
                af[mt][3] = sE[(rb + 8) * 132 + km + t4 + 4];
            }
#pragma unroll
            for (int nt = 0; nt < 4; nt++) {
                int cb = wn * 32 + nt * 8 + g;
                bf[nt][0] = f2tf32(fWV[cb * 132 + km + t4    ]);
                bf[nt][1] = f2tf32(fWV[cb * 132 + km + t4 + 4]);
            }
#pragma unroll
            for (int mt = 0; mt < 4; mt++)
#pragma unroll
                for (int nt = 0; nt < 4; nt++)
                    mma_tf32(yacc[mt][nt], af[mt], bf[nt]);
        }
        __syncthreads();  // before next m-tile overwrites E/WV
    }

    // ---- denominators ----
    rs_sm[rshalf * 128 + rsrow] = rs;
    __syncthreads();

    // ---- scale by 1/den, transpose into E buffer as [c][n] stride 132 ----
    float* const fT = (float*)sE;
#pragma unroll
    for (int mt = 0; mt < 4; mt++)
#pragma unroll
        for (int half = 0; half < 2; half++) {
            int i = wm * 64 + mt * 16 + g + half * 8;
            float inv = 1.f / (rs_sm[i] + rs_sm[128 + i]);
#pragma unroll
            for (int nt = 0; nt < 4; nt++) {
                int j = wn * 32 + nt * 8 + t4 * 2;
                fT[(j    ) * 132 + i] = yacc[mt][nt][half * 2 + 0] * inv;
                fT[(j + 1) * 132 + i] = yacc[mt][nt][half * 2 + 1] * inv;
            }
        }
    __syncthreads();

    // ---- coalesced writeout with bias + residual ----
#pragma unroll
    for (int it = 0; it < 16; it++) {
        int q = tid + it * 256;
        int r = q >> 5, n4 = (q & 31) << 2;
        int c = c0 + r;
        float bi = bo[c];
        const float* tr = fT + r * 132 + n4;
        float4 xv = *(const float4*)(x + (size_t)c * N_ + n0 + n4);
        float4 v;
        v.x = tr[0] + bi + xv.x;
        v.y = tr[1] + bi + xv.y;
        v.z = tr[2] + bi + xv.z;
        v.w = tr[3] + bi + xv.w;
        *(float4*)(yout + (size_t)c * N_ + n0 + n4) = v;
    }
}

// ---------------- mean over N per (b,c) ----------------
__global__ void mean_kernel(const float* __restrict__ x) {
    int bc = blockIdx.x;
    const float* row = x + (size_t)bc * N_;
    float s = 0.f;
    for (int n = threadIdx.x; n < N_; n += 256) s += row[n];
    __shared__ float sh[256];
    sh[threadIdx.x] = s;
    __syncthreads();
    for (int o = 128; o > 0; o >>= 1) {
        if (threadIdx.x < o) sh[threadIdx.x] += sh[threadIdx.x + o];
        __syncthreads();
    }
    if (threadIdx.x == 0) g_mean[bc] = sh[0] * (1.f / N_);
}

// ---------------- variation score per (b,n) ----------------
__global__ void score_kernel(const float* __restrict__ x) {
    int b = blockIdx.y;
    int n = blockIdx.x * 256 + threadIdx.x;
    const float* xb = x + (size_t)b * C_ * N_;
    const float* mb = g_mean + b * C_;
    float acc = 0.f;
#pragma unroll 4
    for (int c = 0; c < C_; c++) {
        float v = xb[(size_t)c * N_ + n] - mb[c];
        acc += v * v;
    }
    g_score[b * N_ + n] = acc;
}

// ---------------- per-batch bitonic full sort ----------------
__global__ void topk_kernel() {
    __shared__ float sk[N_];
    __shared__ int   sv[N_];
    int b = blockIdx.x;
    int t = threadIdx.x;
    for (int i = t; i < N_; i += 1024) {
        sk[i] = g_score[b * N_ + i];
        sv[i] = i;
    }
    __syncthreads();
    for (int k = 2; k <= N_; k <<= 1) {
        for (int j = k >> 1; j > 0; j >>= 1) {
            for (int i = t; i < N_; i += 1024) {
                int ixj = i ^ j;
                if (ixj > i) {
                    bool up = ((i & k) == 0);
                    float a = sk[i], c = sk[ixj];
                    bool sw = up ? (a > c) : (a < c);
                    if (sw) {
                        sk[i] = c; sk[ixj] = a;
                        int tv = sv[i]; sv[i] = sv[ixj]; sv[ixj] = tv;
                    }
                }
            }
            __syncthreads();
        }
    }
    if (t < M_) {
        g_idx[b * 2 * M_ + t]      = sv[N_ - 1 - t];  // sharp
        g_idx[b * 2 * M_ + M_ + t] = sv[t];           // gentle
    }
}

// ---------------- gather selected columns (both sets in one launch) -------
__global__ void gather_kernel(const float* __restrict__ x) {
    int m = blockIdx.x * 256 + threadIdx.x;
    int c = blockIdx.y;
    int b = blockIdx.z >> 1;
    int which = blockIdx.z & 1;
    const int* idx = g_idx + b * 2 * M_ + which * M_;
    float v = x[((size_t)b * C_ + c) * N_ + idx[m]];
    float* dst = which ? g_Xg : g_Xs;
    dst[((size_t)b * C_ + c) * M_ + m] = v;
}

// ---------------- per-channel batch stats ----------------
__global__ void chanstat_kernel() {
    int d = blockIdx.x;
    float s = 0.f, s2 = 0.f;
    for (int b = 0; b < B_; b++) {
        const float* row = g_Z + ((size_t)b * C_ + d) * N_;
        for (int n = threadIdx.x; n < N_; n += 256) {
            float v = row[n];
            s += v;
            s2 += v * v;
        }
    }
    __shared__ float shs[256];
    __shared__ float shq[256];
    shs[threadIdx.x] = s;
    shq[threadIdx.x] = s2;
    __syncthreads();
    for (int o = 128; o > 0; o >>= 1) {
        if (threadIdx.x < o) {
            shs[threadIdx.x] += shs[threadIdx.x + o];
            shq[threadIdx.x] += shq[threadIdx.x + o];
        }
        __syncthreads();
    }
    if (threadIdx.x == 0) {
        const float invBN = 1.f / (float)(B_ * N_);
        float mu = shs[0] * invBN;
        float var = shq[0] * invBN - mu * mu;
        g_mu[d] = mu;
        g_rstd[d] = rsqrtf(var + EPS_);
    }
}

// ---------------- BN + ReLU ----------------
__global__ void bnrelu_kernel(const float* __restrict__ gamma,
                              const float* __restrict__ beta,
                              float* __restrict__ out) {
    size_t i = (size_t)blockIdx.x * 256 + threadIdx.x;
    int d = (int)((i / N_) % C_);
    float v = (g_Z[i] - g_mu[d]) * g_rstd[d] * gamma[d] + beta[d];
    out[i] = fmaxf(v, 0.f);
}

// ---------------- host side ------------------------------------------------
static float* sym_f(const void* s) {
    void* p = nullptr;
    cudaGetSymbolAddress(&p, s);
    return (float*)p;
}

static constexpr int GEMM_SMEM = 4 * OPW * 4;  // 73728 bytes

static void launch_tc(const float* A, long Ab, long As0, long As1,
                      const float* Bp, long Bb, long Bs0, long Bs1,
                      float* Cp, long Cb, long Cs0,
                      const float* bias,
                      float scale, int accumulate, int Md, int Nd, int Kd) {
    dim3 grid(Nd / BN, Md / BM, B_);
    tc_gemm_kernel<<<grid, 128, GEMM_SMEM>>>(
        A, Ab, As0, As1, Bp, Bb, Bs0, Bs1, Cp, Cb, Cs0,
        bias, scale, accumulate, Kd);
}

extern "C" void kernel_launch(void* const* d_in, const int* in_sizes, int n_in,
                              void* d_out, int out_size) {
    static bool attr_done = false;
    if (!attr_done) {
        cudaFuncSetAttribute(tc_gemm_kernel,
                             cudaFuncAttributeMaxDynamicSharedMemorySize, GEMM_SMEM);
        cudaFuncSetAttribute(attn_kernel,
                             cudaFuncAttributeMaxDynamicSharedMemorySize, ATTN_SMEM);
        attr_done = true;
    }

    const float* P[24];
    int p = 0;
    for (int i = 0; i < n_in && p < 24; i++) {
        if (in_sizes[i] == 1) continue;  // num_select scalar
        P[p++] = (const float*)d_in[i];
    }
    const float* x = P[0];
    const float* Wq[2] = {P[1], P[9]};
    const float* bq[2] = {P[2], P[10]};
    const float* Wk[2] = {P[3], P[11]};
    const float* bk[2] = {P[4], P[12]};
    const float* Wv[2] = {P[5], P[13]};
    const float* bv[2] = {P[6], P[14]};
    const float* Wo[2] = {P[7], P[15]};
    const float* bo[2] = {P[8], P[16]};
    const float* Wf = P[17];
    const float* bf = P[18];
    const float* gamma = P[19];
    const float* beta = P[20];
    float* out = (float*)d_out;

    float* Q  = sym_f(g_Q);
    float* K  = sym_f(g_K);
    float* V  = sym_f(g_V);
    float* WV = sym_f(g_WV);
    float* Xs = sym_f(g_Xs);
    float* Xg = sym_f(g_Xg);
    float* ys = sym_f(g_ys);
    float* yg = sym_f(g_yg);
    float* Z  = sym_f(g_Z);

    const long xB = (long)C_ * N_;
    const long cM = (long)C_ * M_;

    // 1) geometry disentangle
    mean_kernel<<<B_ * C_, 256>>>(x);
    score_kernel<<<dim3(N_ / 256, B_), 256>>>(x);
    topk_kernel<<<B_, 1024>>>();
    gather_kernel<<<dim3(M_ / 256, C_, 2 * B_), 256>>>(x);

    // 2) two cross-attentions
    for (int a = 0; a < 2; a++) {
        const float* Xctx = (a == 0) ? Xs : Xg;
        float* ybuf = (a == 0) ? ys : yg;

        // K[d,m] = Wk@Xctx + bk
        launch_tc(Wk[a], 0, C_, 1, Xctx, cM, 1, M_, K, cM, M_,
                  bk[a], 1.f, 0, C_, M_, C_);
        // Q[d,n] = (Wq@x + bq)/16
        launch_tc(Wq[a], 0, C_, 1, x, xB, 1, N_, Q, xB, N_,
                  bq[a], 0.0625f, 0, C_, N_, C_);
        // V[d,m] = Wv@Xctx + bv
        launch_tc(Wv[a], 0, C_, 1, Xctx, cM, 1, M_, V, cM, M_,
                  bv[a], 1.f, 0, C_, M_, C_);
        // WV[e,m] = Wo @ V
        launch_tc(Wo[a], 0, C_, 1, V, cM, 1, M_, WV, cM, M_,
                  nullptr, 1.f, 0, C_, M_, C_);
        // fused attention: y = softmax(Q^T K) applied, + bo + x
        attn_kernel<<<dim3(N_ / 128, C_ / 128, B_), 256, ATTN_SMEM>>>(
            Q, K, WV, x, bo[a], ybuf);
    }

    // 3) fuse: Z = Wf[:, :C]@ys + Wf[:, C:]@yg + bf
    launch_tc(Wf, 0, 2 * C_, 1, ys, xB, 1, N_, Z, xB, N_,
              nullptr, 1.f, 0, C_, N_, C_);
    launch_tc(Wf + C_, 0, 2 * C_, 1, yg, xB, 1, N_, Z, xB, N_,
              bf, 1.f, 1, C_, N_, C_);

    // 4) batch-norm (training stats) + ReLU
    chanstat_kernel<<<C_, 256>>>();
    bnrelu_kernel<<<(B_ * C_ * N_) / 256, 256>>>(gamma, beta, out);
}

// round 7
// speedup vs baseline: 1.3696x; 1.3696x over previous
#include <cuda_runtime.h>
#include <cstdint>
#include <math.h>

// Problem dims (fixed by the reference)
static constexpr int B_ = 16;
static constexpr int C_ = 256;
static constexpr int N_ = 4096;
static constexpr int M_ = 1024;
static constexpr float EPS_ = 1e-5f;

// ---------------- scratch (static device globals; no allocation) ----------
__device__ float g_mean[B_ * C_];
__device__ float g_score[B_ * N_];
__device__ int   g_idx[B_ * 2 * M_];
__device__ float g_Xs[(size_t)B_ * C_ * M_];
__device__ float g_Xg[(size_t)B_ * C_ * M_];
__device__ float g_Q[(size_t)B_ * C_ * N_];
__device__ float g_K[(size_t)B_ * C_ * M_];
__device__ float g_WV[(size_t)B_ * C_ * M_];  // (Wo@Wv)@Xctx + Wo@bv
__device__ float g_S[(size_t)B_ * N_ * M_];   // E = exp(scores)
__device__ float g_ys[(size_t)B_ * C_ * N_];
__device__ float g_yg[(size_t)B_ * C_ * N_];
__device__ float g_Z[(size_t)B_ * C_ * N_];
__device__ float g_den[2 * B_ * N_];          // softmax denominators (2 attns)
__device__ float g_Wow[2 * C_ * C_];          // Wo @ Wv per attention
__device__ float g_bov[2 * C_];               // Wo @ bv per attention
__device__ float g_mu[C_];
__device__ float g_rstd[C_];

// ---------------- helpers --------------------------------------------------
// NOTE: no explicit cvt.rna.tf32 on fragments — mma.tf32 reads the tf32
// subset of the b32 register (truncation); error bound stays ~2^-11.
__device__ __forceinline__ void mma_tf32(float* c, const uint32_t* a, const uint32_t* b) {
    asm volatile(
        "mma.sync.aligned.m16n8k8.row.col.f32.tf32.tf32.f32 "
        "{%0,%1,%2,%3}, {%4,%5,%6,%7}, {%8,%9}, {%0,%1,%2,%3};"
        : "+f"(c[0]), "+f"(c[1]), "+f"(c[2]), "+f"(c[3])
        : "r"(a[0]), "r"(a[1]), "r"(a[2]), "r"(a[3]), "r"(b[0]), "r"(b[1]));
}
__device__ __forceinline__ uint32_t smem_u32(const void* p) {
    uint32_t a;
    asm("{ .reg .u64 t; cvta.to.shared.u64 t, %1; cvt.u32.u64 %0, t; }"
        : "=r"(a) : "l"(p));
    return a;
}
__device__ __forceinline__ void cp16(uint32_t saddr, const float* g) {
    asm volatile("cp.async.cg.shared.global [%0], [%1], 16;" :: "r"(saddr), "l"(g));
}

// ================== pipelined warp-MMA tf32 generic strided GEMM ==========
// Normal: D[i,j] = scale*acc [*colscale[j]] + scale*bias[i] [+addend] [+D_old]
// Exp mode (rowsum != nullptr):
//   D[i,j] = exp(acc[i,j]); rowsum[i] += sum_j D[i,j] (atomic)
// A(i,k) = A[i*As0 + k*As1]; B(j,k) = B[j*Bs0 + k*Bs1]; one stride is 1.
// Block tile 128x128, 4 warps (64x64 each), BK=32. Md,Nd %128; Kd %32.
#define BM 128
#define BN 128
#define BK 32
#define SKC 36   // smem row stride (words), k-contig layout [i][k]
#define SIC 136  // smem row stride (words), i-contig layout [k][i]
#define OPW 4608 // words per operand per stage = max(128*36, 32*136)

__device__ __forceinline__ void stage_tile(const float* __restrict__ src,
                                           long s0, long s1, int kc,
                                           uint32_t sbase, int t0, int kt, int tid) {
    if (kc) {  // k contiguous -> smem [i][k], stride SKC
#pragma unroll
        for (int it = 0; it < 8; it++) {
            int q = tid + it * 128;
            int row = q >> 3, kq = (q & 7) << 2;
            cp16(sbase + (uint32_t)(row * SKC + kq) * 4u,
                 src + (long)(t0 + row) * s0 + kt + kq);
        }
    } else {   // i contiguous -> smem [k][i], stride SIC
#pragma unroll
        for (int it = 0; it < 8; it++) {
            int q = tid + it * 128;
            int kr = q >> 5, iq = (q & 31) << 2;
            cp16(sbase + (uint32_t)(kr * SIC + iq) * 4u,
                 src + (long)(t0 + iq) + (long)(kt + kr) * s1);
        }
    }
}

__global__ void __launch_bounds__(128, 2)
tc_gemm_kernel(const float* __restrict__ A, long Ab, long As0, long As1,
               const float* __restrict__ Bp, long Bb, long Bs0, long Bs1,
               float* __restrict__ Cp, long Cb, long Cs0,
               const float* __restrict__ bias,
               const float* __restrict__ addend, long Addb,
               float* rowsum, long Rsb,
               const float* __restrict__ colscale, long Csb,
               float scale, int accumulate, int Kd) {
    extern __shared__ uint32_t sm[];

    const int tid = threadIdx.x;
    const int wid = tid >> 5;
    const int lane = tid & 31;
    const int g = lane >> 2;
    const int t4 = lane & 3;
    const int wm = wid & 1;    // warp row (64 rows)
    const int wn = wid >> 1;   // warp col (64 cols)

    const int aKc = (As1 == 1);
    const int bKc = (Bs1 == 1);

    const int bz = blockIdx.z;
    A += (size_t)bz * Ab;
    Bp += (size_t)bz * Bb;
    Cp += (size_t)bz * Cb;
    if (addend) addend += (size_t)bz * Addb;
    if (rowsum) rowsum += (size_t)bz * Rsb;
    if (colscale) colscale += (size_t)bz * Csb;

    const int i0 = blockIdx.y * BM;
    const int j0 = blockIdx.x * BN;

    const uint32_t smbase = smem_u32(sm);

    float acc[4][8][4];
#pragma unroll
    for (int a = 0; a < 4; a++)
#pragma unroll
        for (int b = 0; b < 8; b++)
#pragma unroll
            for (int c = 0; c < 4; c++) acc[a][b][c] = 0.f;

    const int nch = Kd >> 5;

    stage_tile(A, As0, As1, aKc, smbase, i0, 0, tid);
    stage_tile(Bp, Bs0, Bs1, bKc, smbase + OPW * 4u, j0, 0, tid);
    asm volatile("cp.async.commit_group;" ::: "memory");

    for (int ch = 0; ch < nch; ch++) {
        if (ch + 1 < nch) {
            uint32_t sb = smbase + (uint32_t)(((ch + 1) & 1) * 2 * OPW) * 4u;
            stage_tile(A, As0, As1, aKc, sb, i0, (ch + 1) * BK, tid);
            stage_tile(Bp, Bs0, Bs1, bKc, sb + OPW * 4u, j0, (ch + 1) * BK, tid);
        }
        asm volatile("cp.async.commit_group;" ::: "memory");
        asm volatile("cp.async.wait_group 1;" ::: "memory");
        __syncthreads();

        const uint32_t* sA = sm + (ch & 1) * 2 * OPW;
        const uint32_t* sB = sA + OPW;

#pragma unroll
        for (int ks = 0; ks < BK; ks += 8) {
            uint32_t af[4][4];
            if (aKc) {
#pragma unroll
                for (int mt = 0; mt < 4; mt++) {
                    int rb = wm * 64 + mt * 16 + g;
                    af[mt][0] = sA[(rb    ) * SKC + ks + t4    ];
                    af[mt][1] = sA[(rb + 8) * SKC + ks + t4    ];
                    af[mt][2] = sA[(rb    ) * SKC + ks + t4 + 4];
                    af[mt][3] = sA[(rb + 8) * SKC + ks + t4 + 4];
                }
            } else {
#pragma unroll
                for (int mt = 0; mt < 4; mt++) {
                    int rb = wm * 64 + mt * 16 + g;
                    af[mt][0] = sA[(ks + t4    ) * SIC + rb    ];
                    af[mt][1] = sA[(ks + t4    ) * SIC + rb + 8];
                    af[mt][2] = sA[(ks + t4 + 4) * SIC + rb    ];
                    af[mt][3] = sA[(ks + t4 + 4) * SIC + rb + 8];
                }
            }
            uint32_t bf[8][2];
            if (bKc) {
#pragma unroll
                for (int nt = 0; nt < 8; nt++) {
                    int cb = wn * 64 + nt * 8 + g;
                    bf[nt][0] = sB[(cb) * SKC + ks + t4    ];
                    bf[nt][1] = sB[(cb) * SKC + ks + t4 + 4];
                }
            } else {
#pragma unroll
                for (int nt = 0; nt < 8; nt++) {
                    int cb = wn * 64 + nt * 8 + g;
                    bf[nt][0] = sB[(ks + t4    ) * SIC + cb];
                    bf[nt][1] = sB[(ks + t4 + 4) * SIC + cb];
                }
            }
#pragma unroll
            for (int mt = 0; mt < 4; mt++)
#pragma unroll
                for (int nt = 0; nt < 8; nt++)
                    mma_tf32(acc[mt][nt], af[mt], bf[nt]);
        }
        __syncthreads();
    }

    // ---- epilogue ----
    if (rowsum) {
#pragma unroll
        for (int mt = 0; mt < 4; mt++) {
#pragma unroll
            for (int half = 0; half < 2; half++) {
                int i = i0 + wm * 64 + mt * 16 + g + half * 8;
                float rs = 0.f;
#pragma unroll
                for (int nt = 0; nt < 8; nt++) {
                    int j = j0 + wn * 64 + nt * 8 + t4 * 2;
                    float e0 = __expf(acc[mt][nt][half * 2 + 0]);
                    float e1 = __expf(acc[mt][nt][half * 2 + 1]);
                    *(float2*)(Cp + (long)i * Cs0 + j) = make_float2(e0, e1);
                    rs += e0 + e1;
                }
                rs += __shfl_xor_sync(0xffffffffu, rs, 1);
                rs += __shfl_xor_sync(0xffffffffu, rs, 2);
                if (t4 == 0) atomicAdd(&rowsum[i], rs);
            }
        }
        return;
    }
#pragma unroll
    for (int mt = 0; mt < 4; mt++) {
#pragma unroll
        for (int half = 0; half < 2; half++) {
            int i = i0 + wm * 64 + mt * 16 + g + half * 8;
            float bi = bias ? scale * bias[i] : 0.f;
#pragma unroll
            for (int nt = 0; nt < 8; nt++) {
                int j = j0 + wn * 64 + nt * 8 + t4 * 2;
                long off = (long)i * Cs0 + j;
                float2 v;
                v.x = scale * acc[mt][nt][half * 2 + 0];
                v.y = scale * acc[mt][nt][half * 2 + 1];
                if (colscale) {
                    v.x *= colscale[j];
                    v.y *= colscale[j + 1];
                }
                v.x += bi; v.y += bi;
                if (addend) {
                    float2 a2 = *(const float2*)(addend + off);
                    v.x += a2.x; v.y += a2.y;
                }
                if (accumulate) {
                    float2 o2 = *(const float2*)(Cp + off);
                    v.x += o2.x; v.y += o2.y;
                }
                *(float2*)(Cp + off) = v;
            }
        }
    }
}

// ---------------- bov = Wo @ bv (per attention) ----------------
__global__ void bov_kernel(const float* __restrict__ Wo,
                           const float* __restrict__ bv, int a) {
    int e = threadIdx.x;  // 256 threads
    const float* row = Wo + e * C_;
    float s = 0.f;
#pragma unroll 8
    for (int c = 0; c < C_; c++) s += row[c] * bv[c];
    g_bov[a * C_ + e] = s;
}

// ---------------- invert softmax denominators in place ----------------
__global__ void invden_kernel(int a) {
    int i = blockIdx.x * 256 + threadIdx.x;
    g_den[a * B_ * N_ + i] = 1.f / g_den[a * B_ * N_ + i];
}

// ---------------- mean over N per (b,c) ----------------
__global__ void mean_kernel(const float* __restrict__ x) {
    int bc = blockIdx.x;
    const float* row = x + (size_t)bc * N_;
    float s = 0.f;
    for (int n = threadIdx.x; n < N_; n += 256) s += row[n];
    __shared__ float sh[256];
    sh[threadIdx.x] = s;
    __syncthreads();
    for (int o = 128; o > 0; o >>= 1) {
        if (threadIdx.x < o) sh[threadIdx.x] += sh[threadIdx.x + o];
        __syncthreads();
    }
    if (threadIdx.x == 0) g_mean[bc] = sh[0] * (1.f / N_);
}

// ---------------- variation score per (b,n); also zeros denominators ------
__global__ void score_kernel(const float* __restrict__ x) {
    int b = blockIdx.y;
    int n = blockIdx.x * 256 + threadIdx.x;
    const float* xb = x + (size_t)b * C_ * N_;
    const float* mb = g_mean + b * C_;
    float acc = 0.f;
#pragma unroll 4
    for (int c = 0; c < C_; c++) {
        float v = xb[(size_t)c * N_ + n] - mb[c];
        acc += v * v;
    }
    int gi = b * N_ + n;
    g_score[gi] = acc;
    g_den[gi] = 0.f;
    g_den[B_ * N_ + gi] = 0.f;
}

// ---------------- per-batch bitonic full sort ----------------
__global__ void topk_kernel() {
    __shared__ float sk[N_];
    __shared__ int   sv[N_];
    int b = blockIdx.x;
    int t = threadIdx.x;
    for (int i = t; i < N_; i += 1024) {
        sk[i] = g_score[b * N_ + i];
        sv[i] = i;
    }
    __syncthreads();
    for (int k = 2; k <= N_; k <<= 1) {
        for (int j = k >> 1; j > 0; j >>= 1) {
            for (int i = t; i < N_; i += 1024) {
                int ixj = i ^ j;
                if (ixj > i) {
                    bool up = ((i & k) == 0);
                    float a = sk[i], c = sk[ixj];
                    bool sw = up ? (a > c) : (a < c);
                    if (sw) {
                        sk[i] = c; sk[ixj] = a;
                        int tv = sv[i]; sv[i] = sv[ixj]; sv[ixj] = tv;
                    }
                }
            }
            __syncthreads();
        }
    }
    if (t < M_) {
        g_idx[b * 2 * M_ + t]      = sv[N_ - 1 - t];  // sharp
        g_idx[b * 2 * M_ + M_ + t] = sv[t];           // gentle
    }
}

// ---------------- gather selected columns (both sets in one launch) -------
__global__ void gather_kernel(const float* __restrict__ x) {
    int m = blockIdx.x * 256 + threadIdx.x;
    int c = blockIdx.y;
    int b = blockIdx.z >> 1;
    int which = blockIdx.z & 1;
    const int* idx = g_idx + b * 2 * M_ + which * M_;
    float v = x[((size_t)b * C_ + c) * N_ + idx[m]];
    float* dst = which ? g_Xg : g_Xs;
    dst[((size_t)b * C_ + c) * M_ + m] = v;
}

// ---------------- per-channel batch stats ----------------
__global__ void chanstat_kernel() {
    int d = blockIdx.x;
    float s = 0.f, s2 = 0.f;
    for (int b = 0; b < B_; b++) {
        const float* row = g_Z + ((size_t)b * C_ + d) * N_;
        for (int n = threadIdx.x; n < N_; n += 256) {
            float v = row[n];
            s += v;
            s2 += v * v;
        }
    }
    __shared__ float shs[256];
    __shared__ float shq[256];
    shs[threadIdx.x] = s;
    shq[threadIdx.x] = s2;
    __syncthreads();
    for (int o = 128; o > 0; o >>= 1) {
        if (threadIdx.x < o) {
            shs[threadIdx.x] += shs[threadIdx.x + o];
            shq[threadIdx.x] += shq[threadIdx.x + o];
        }
        __syncthreads();
    }
    if (threadIdx.x == 0) {
        const float invBN = 1.f / (float)(B_ * N_);
        float mu = shs[0] * invBN;
        float var = shq[0] * invBN - mu * mu;
        g_mu[d] = mu;
        g_rstd[d] = rsqrtf(var + EPS_);
    }
}

// ---------------- BN + ReLU ----------------
__global__ void bnrelu_kernel(const float* __restrict__ gamma,
                              const float* __restrict__ beta,
                              float* __restrict__ out) {
    size_t i = (size_t)blockIdx.x * 256 + threadIdx.x;
    int d = (int)((i / N_) % C_);
    float v = (g_Z[i] - g_mu[d]) * g_rstd[d] * gamma[d] + beta[d];
    out[i] = fmaxf(v, 0.f);
}

// ---------------- host side ------------------------------------------------
static float* sym_f(const void* s) {
    void* p = nullptr;
    cudaGetSymbolAddress(&p, s);
    return (float*)p;
}

static constexpr int GEMM_SMEM = 4 * OPW * 4;  // 73728 bytes

static void launch_tc(const float* A, long Ab, long As0, long As1,
                      const float* Bp, long Bb, long Bs0, long Bs1,
                      float* Cp, long Cb, long Cs0,
                      const float* bias, const float* addend, long Addb,
                      float* rowsum, long Rsb,
                      const float* colscale, long Csb,
                      float scale, int accumulate, int Md, int Nd, int Kd,
                      int nbatch) {
    dim3 grid(Nd / BN, Md / BM, nbatch);
    tc_gemm_kernel<<<grid, 128, GEMM_SMEM>>>(
        A, Ab, As0, As1, Bp, Bb, Bs0, Bs1, Cp, Cb, Cs0,
        bias, addend, Addb, rowsum, Rsb, colscale, Csb,
        scale, accumulate, Kd);
}

extern "C" void kernel_launch(void* const* d_in, const int* in_sizes, int n_in,
                              void* d_out, int out_size) {
    static bool attr_done = false;
    if (!attr_done) {
        cudaFuncSetAttribute(tc_gemm_kernel,
                             cudaFuncAttributeMaxDynamicSharedMemorySize, GEMM_SMEM);
        attr_done = true;
    }

    const float* P[24];
    int p = 0;
    for (int i = 0; i < n_in && p < 24; i++) {
        if (in_sizes[i] == 1) continue;  // num_select scalar
        P[p++] = (const float*)d_in[i];
    }
    const float* x = P[0];
    const float* Wq[2] = {P[1], P[9]};
    const float* bq[2] = {P[2], P[10]};
    const float* Wk[2] = {P[3], P[11]};
    const float* bk[2] = {P[4], P[12]};
    const float* Wv[2] = {P[5], P[13]};
    const float* bv[2] = {P[6], P[14]};
    const float* Wo[2] = {P[7], P[15]};
    const float* bo[2] = {P[8], P[16]};
    const float* Wf = P[17];
    const float* bf = P[18];
    const float* gamma = P[19];
    const float* beta = P[20];
    float* out = (float*)d_out;

    float* Q   = sym_f(g_Q);
    float* K   = sym_f(g_K);
    float* WV  = sym_f(g_WV);
    float* S   = sym_f(g_S);
    float* Xs  = sym_f(g_Xs);
    float* Xg  = sym_f(g_Xg);
    float* ys  = sym_f(g_ys);
    float* yg  = sym_f(g_yg);
    float* Z   = sym_f(g_Z);
    float* den = sym_f(g_den);
    float* Wow = sym_f(g_Wow);
    float* bov = sym_f(g_bov);

    const long xB = (long)C_ * N_;
    const long cM = (long)C_ * M_;
    const long sB = (long)N_ * M_;

    // 1) geometry disentangle (launches 0-3)
    mean_kernel<<<B_ * C_, 256>>>(x);
    score_kernel<<<dim3(N_ / 256, B_), 256>>>(x);  // also zeros g_den
    topk_kernel<<<B_, 1024>>>();
    gather_kernel<<<dim3(M_ / 256, C_, 2 * B_), 256>>>(x);

    // 2) two cross-attentions
    for (int a = 0; a < 2; a++) {
        const float* Xctx = (a == 0) ? Xs : Xg;
        float* ybuf = (a == 0) ? ys : yg;
        float* dena = den + a * B_ * N_;
        float* Wowa = Wow + a * C_ * C_;
        float* bova = bov + a * C_;

        // K[d,m] = Wk@Xctx + bk                              (launch 4)
        launch_tc(Wk[a], 0, C_, 1, Xctx, cM, 1, M_, K, cM, M_,
                  bk[a], nullptr, 0, nullptr, 0, nullptr, 0,
                  1.f, 0, C_, M_, C_, B_);
        // Q[d,n] = (Wq@x + bq)/16                            (launch 5: profiled)
        launch_tc(Wq[a], 0, C_, 1, x, xB, 1, N_, Q, xB, N_,
                  bq[a], nullptr, 0, nullptr, 0, nullptr, 0,
                  0.0625f, 0, C_, N_, C_, B_);
        // Wow[e,c2] = sum_c Wo[e,c] Wv[c,c2]   (B(j=c2,k=c): Bs0=1, Bs1=C)
        launch_tc(Wo[a], 0, C_, 1, Wv[a], 0, 1, C_, Wowa, 0, C_,
                  nullptr, nullptr, 0, nullptr, 0, nullptr, 0,
                  1.f, 0, C_, C_, C_, 1);
        bov_kernel<<<1, 256>>>(Wo[a], bv[a], a);
        // E[n,m] = exp(sum_d Q[d,n] K[d,m]); den[b,n] += row sums
        launch_tc(Q, xB, 1, N_, K, cM, 1, M_, S, sB, M_,
                  nullptr, nullptr, 0, dena, N_, nullptr, 0,
                  1.f, 0, N_, M_, C_, B_);
        invden_kernel<<<(B_ * N_) / 256, 256>>>(a);
        // WV[e,m] = Wow@Xctx + bov
        launch_tc(Wowa, 0, C_, 1, Xctx, cM, 1, M_, WV, cM, M_,
                  bova, nullptr, 0, nullptr, 0, nullptr, 0,
                  1.f, 0, C_, M_, C_, B_);
        // y[e,n] = (sum_m WV[e,m] E[n,m]) * invden[b,n] + bo[e] + x[e,n]
        launch_tc(WV, cM, M_, 1, S, sB, M_, 1, ybuf, xB, N_,
                  bo[a], x, xB, nullptr, 0, dena, N_,
                  1.f, 0, C_, N_, M_, B_);
    }

    // 3) fuse: Z = Wf[:, :C]@ys + Wf[:, C:]@yg + bf
    launch_tc(Wf, 0, 2 * C_, 1, ys, xB, 1, N_, Z, xB, N_,
              nullptr, nullptr, 0, nullptr, 0, nullptr, 0,
              1.f, 0, C_, N_, C_, B_);
    launch_tc(Wf + C_, 0, 2 * C_, 1, yg, xB, 1, N_, Z, xB, N_,
              bf, nullptr, 0, nullptr, 0, nullptr, 0,
              1.f, 1, C_, N_, C_, B_);

    // 4) batch-norm (training stats) + ReLU
    chanstat_kernel<<<C_, 256>>>();
    bnrelu_kernel<<<(B_ * C_ * N_) / 256, 256>>>(gamma, beta, out);
}